// round 9
// baseline (speedup 1.0000x reference)
#include <cuda_runtime.h>
#include <cuda_bf16.h>

#define N_EXPERTS 32
#define H 256
#define BATCH 16
#define SEQ 8192
#define ALPHA 0.001f

#define TPB_TOKENS 64           // tokens per block (wave-quantization fix: grid 2048)
#define TILE 8                  // tokens per pipeline tile
#define NTILES (TPB_TOKENS / TILE)   // 8
#define STAGES 3
#define XROW 288                // words per token row in xbuf (256 data + skew pads)
#define XTILE (TILE * XROW)     // 2304 words per stage
#define PSTR 5                  // partials per logit (4) + 1 pad
#define PARTW (TILE * N_EXPERTS * PSTR)   // 1280 words per part buffer
#define NBLOCKS 2048
#define BLK_PER_BATCH 128

// Per-block aux partials (written every launch -> no zeroing pass needed).
__device__ float g_bsum[NBLOCKS * N_EXPERTS];
__device__ float g_bcnt[NBLOCKS * N_EXPERTS];
__device__ unsigned g_ctr = 0;          // last-block-done counter (self-resetting)

// ---- packed f32x2 helpers (Blackwell) ----
__device__ __forceinline__ unsigned long long f2_mul(unsigned long long a, unsigned long long b) {
    unsigned long long d;
    asm("mul.rn.f32x2 %0, %1, %2;" : "=l"(d) : "l"(a), "l"(b));
    return d;
}
__device__ __forceinline__ unsigned long long f2_fma(unsigned long long a, unsigned long long b,
                                                     unsigned long long c) {
    unsigned long long d;
    asm("fma.rn.f32x2 %0, %1, %2, %3;" : "=l"(d) : "l"(a), "l"(b), "l"(c));
    return d;
}
__device__ __forceinline__ float f2_hadd(unsigned long long a) {
    unsigned lo, hi;
    asm("mov.b64 {%0, %1}, %2;" : "=r"(lo), "=r"(hi) : "l"(a));
    return __uint_as_float(lo) + __uint_as_float(hi);
}
__device__ __forceinline__ void ldg_v2u64(const float* p, unsigned long long& a,
                                          unsigned long long& b) {
    asm("ld.global.nc.v2.b64 {%0, %1}, [%2];" : "=l"(a), "=l"(b) : "l"(p));
}

// ---- cp.async helpers ----
__device__ __forceinline__ void cp_async16(void* smem_dst, const void* gsrc) {
    unsigned saddr = (unsigned)__cvta_generic_to_shared(smem_dst);
    asm volatile("cp.async.cg.shared.global [%0], [%1], 16;" :: "r"(saddr), "l"(gsrc));
}
#define CP_COMMIT()  asm volatile("cp.async.commit_group;")
#define CP_WAIT(N)   asm volatile("cp.async.wait_group %0;" :: "n"(N))

// MoE gate: 4 warps, W-stationary, 2 experts/lane.
// Lane L of warp WI holds experts {L&15, (L&15)+16} over k-slice 32*(2*WI+(L>>4)).
// x tile staged via cp.async with +16B skew per 128B so each LDS.128 serves the
// two 16-lane groups from disjoint banks (dual broadcast, conflict-free).
__global__ __launch_bounds__(128, 5)
void gate_kernel(const float* __restrict__ x, const float* __restrict__ w,
                 float* __restrict__ out_idx, float* __restrict__ out_w,
                 float* __restrict__ out_aux) {
    __shared__ float xbuf[STAGES * XTILE];   // 27.6 KB
    __shared__ float part[2 * PARTW];        // 10.2 KB (double-buffered)
    __shared__ float red4[4];
    __shared__ unsigned s_old;

    const int tid = threadIdx.x;
    const int lane = tid & 31;
    const int wi = tid >> 5;                 // 0..3
    const int grp = lane >> 4;               // 0/1: which k-slice of the pair
    const int bid = blockIdx.x;
    const int tok_base = bid * TPB_TOKENS;

    // Weight regs: expert e0 = lane&15 and e1 = e0+16, k-cols [ks*32, ks*32+32).
    const int ks = 2 * wi + grp;
    unsigned long long w0[16], w1[16];
    {
        const float* wp0 = w + (lane & 15) * H + ks * 32;
        const float* wp1 = wp0 + 16 * H;
        #pragma unroll
        for (int j = 0; j < 8; j++) {
            ldg_v2u64(wp0 + 4 * j, w0[2 * j], w0[2 * j + 1]);
            ldg_v2u64(wp1 + 4 * j, w1[2 * j], w1[2 * j + 1]);
        }
    }

    // cp.async chunk mapping for this thread: 4 chunks/tile.
    // chunk c (0..63) of row r lands at word r*XROW + c*4 + (c>>3)*4.
    const int pf_row = tid >> 4;             // 0..7
    const int pf_c0 = tid & 15;              // +16k, k=0..3
    const float* xg = x + (size_t)tok_base * H;

    // Prologue: prefetch tiles 0,1.
    #pragma unroll
    for (int s = 0; s < STAGES - 1; s++) {
        float* dst = xbuf + s * XTILE + pf_row * XROW;
        const float* src = xg + s * (TILE * H) + pf_row * H;
        #pragma unroll
        for (int k = 0; k < 4; k++) {
            int c = pf_c0 + 16 * k;
            cp_async16(dst + c * 4 + (c >> 3) * 4, src + c * 4);
        }
        CP_COMMIT();
    }

    float score_acc = 0.0f;   // lane == expert (phase B view)
    float cnt_acc = 0.0f;

    for (int t = 0; t < NTILES; t++) {
        CP_WAIT(1);
        __syncthreads();

        // ---------- Phase A ----------
        const float* xb = xbuf + (t % STAGES) * XTILE + ks * 36;  // 36 words = 8 chunks + skew
        float* pb = part + (t & 1) * PARTW;
        #pragma unroll 4
        for (int tok = 0; tok < TILE; tok++) {
            const ulonglong2* xp = (const ulonglong2*)(xb + tok * XROW);
            unsigned long long a0, a1, b0, b1;
            {
                ulonglong2 v0 = xp[0], v1 = xp[1], v2 = xp[2], v3 = xp[3];
                a0 = f2_mul(v0.x, w0[0]);  a1 = f2_mul(v0.y, w0[1]);
                b0 = f2_mul(v0.x, w1[0]);  b1 = f2_mul(v0.y, w1[1]);
                a0 = f2_fma(v1.x, w0[2], a0);  a1 = f2_fma(v1.y, w0[3], a1);
                b0 = f2_fma(v1.x, w1[2], b0);  b1 = f2_fma(v1.y, w1[3], b1);
                a0 = f2_fma(v2.x, w0[4], a0);  a1 = f2_fma(v2.y, w0[5], a1);
                b0 = f2_fma(v2.x, w1[4], b0);  b1 = f2_fma(v2.y, w1[5], b1);
                a0 = f2_fma(v3.x, w0[6], a0);  a1 = f2_fma(v3.y, w0[7], a1);
                b0 = f2_fma(v3.x, w1[6], b0);  b1 = f2_fma(v3.y, w1[7], b1);
            }
            {
                ulonglong2 v4 = xp[4], v5 = xp[5], v6 = xp[6], v7 = xp[7];
                a0 = f2_fma(v4.x, w0[8],  a0);  a1 = f2_fma(v4.y, w0[9],  a1);
                b0 = f2_fma(v4.x, w1[8],  b0);  b1 = f2_fma(v4.y, w1[9],  b1);
                a0 = f2_fma(v5.x, w0[10], a0);  a1 = f2_fma(v5.y, w0[11], a1);
                b0 = f2_fma(v5.x, w1[10], b0);  b1 = f2_fma(v5.y, w1[11], b1);
                a0 = f2_fma(v6.x, w0[12], a0);  a1 = f2_fma(v6.y, w0[13], a1);
                b0 = f2_fma(v6.x, w1[12], b0);  b1 = f2_fma(v6.y, w1[13], b1);
                a0 = f2_fma(v7.x, w0[14], a0);  a1 = f2_fma(v7.y, w0[15], a1);
                b0 = f2_fma(v7.x, w1[14], b0);  b1 = f2_fma(v7.y, w1[15], b1);
            }
            float p0 = f2_hadd(a0) + f2_hadd(a1);          // expert lane&15
            float p1 = f2_hadd(b0) + f2_hadd(b1);          // expert (lane&15)+16
            // combine the two k-slices of the pair (lanes L and L^16 swap)
            p0 += __shfl_xor_sync(0xffffffffu, p0, 16);
            p1 += __shfl_xor_sync(0xffffffffu, p1, 16);
            const float val = (grp == 0) ? p0 : p1;        // store expert == lane
            pb[(tok * N_EXPERTS + lane) * PSTR + wi] = val; // stride-5: conflict-free
        }
        __syncthreads();

        // Prefetch tile t+2.
        if (t + STAGES - 1 < NTILES) {
            float* dst = xbuf + ((t + STAGES - 1) % STAGES) * XTILE + pf_row * XROW;
            const float* src = xg + (t + STAGES - 1) * (TILE * H) + pf_row * H;
            #pragma unroll
            for (int k = 0; k < 4; k++) {
                int c = pf_c0 + 16 * k;
                cp_async16(dst + c * 4 + (c >> 3) * 4, src + c * 4);
            }
        }
        CP_COMMIT();

        // ---------- Phase B: warp wi -> tokens {2wi, 2wi+1} ----------
        #pragma unroll
        for (int tt = 0; tt < 2; tt++) {
            const int tok = wi * 2 + tt;
            const float* pr = pb + (tok * N_EXPERTS + lane) * PSTR;
            float v = (pr[0] + pr[1]) + (pr[2] + pr[3]);   // logit, expert == lane

            float m = v;
            #pragma unroll
            for (int off = 16; off; off >>= 1)
                m = fmaxf(m, __shfl_xor_sync(0xffffffffu, m, off));
            const unsigned bal = __ballot_sync(0xffffffffu, v == m);
            const int mi = __ffs(bal) - 1;                 // lowest index on ties

            const float e = __expf(v - m);
            float s = e;
            #pragma unroll
            for (int off = 16; off; off >>= 1)
                s += __shfl_xor_sync(0xffffffffu, s, off);
            const float inv = __fdividef(1.0f, s);

            score_acc += e * inv;
            if (lane == mi) cnt_acc += 1.0f;
            if (lane == 0) {
                const int gt = tok_base + t * TILE + tok;
                out_idx[gt] = (float)mi;
                out_w[gt] = inv;
            }
        }
    }

    // ---------- Per-block aux partials ----------
    __syncthreads();
    part[wi * 32 + lane] = score_acc;
    part[128 + wi * 32 + lane] = cnt_acc;
    __syncthreads();
    if (wi == 0) {
        float s = (part[lane] + part[32 + lane]) + (part[64 + lane] + part[96 + lane]);
        g_bsum[bid * N_EXPERTS + lane] = s;
        __threadfence();
    }
    if (wi == 1) {
        float c = (part[128 + lane] + part[160 + lane]) + (part[192 + lane] + part[224 + lane]);
        g_bcnt[bid * N_EXPERTS + lane] = c;
        __threadfence();
    }
    __syncthreads();

    // ---------- Last block computes aux loss ----------
    if (tid == 0) s_old = atomicAdd(&g_ctr, 1u);
    __syncthreads();
    if (s_old == (unsigned)(gridDim.x - 1)) {
        __threadfence();
        float acc = 0.0f;
        for (int p = tid; p < BATCH * N_EXPERTS; p += 128) {
            const int b = p >> 5, e = p & 31;
            float sc = 0.0f, cn = 0.0f;
            #pragma unroll 8
            for (int j = 0; j < BLK_PER_BATCH; j++) {
                sc += g_bsum[(b * BLK_PER_BATCH + j) * N_EXPERTS + e];
                cn += g_bcnt[(b * BLK_PER_BATCH + j) * N_EXPERTS + e];
            }
            acc += (cn * ((float)N_EXPERTS / (float)SEQ)) * (sc * (1.0f / (float)SEQ));
        }
        #pragma unroll
        for (int off = 16; off; off >>= 1)
            acc += __shfl_xor_sync(0xffffffffu, acc, off);
        if (lane == 0) red4[wi] = acc;
        __syncthreads();
        if (tid == 0) {
            out_aux[0] = ((red4[0] + red4[1]) + (red4[2] + red4[3])) * (ALPHA / (float)BATCH);
            g_ctr = 0;                                   // reset for next replay
        }
    }
}

extern "C" void kernel_launch(void* const* d_in, const int* in_sizes, int n_in,
                              void* d_out, int out_size) {
    const float* x = (const float*)d_in[0];   // [16, 8192, 256] f32
    const float* w = (const float*)d_in[1];   // [32, 256] f32
    float* out = (float*)d_out;               // [N idx | N weight | 1 aux], f32

    const int n_tokens = in_sizes[0] / H;     // 131072
    const int n_blocks = n_tokens / TPB_TOKENS;   // 2048

    gate_kernel<<<n_blocks, 128>>>(x, w, out, out + n_tokens, out + 2 * n_tokens);
}